// round 14
// baseline (speedup 1.0000x reference)
#include <cuda_runtime.h>

// Problem constants (fixed by setup_inputs)
#define BATCH   16
#define CHAN    4
#define H_IN    128
#define W_IN    240
#define MAXD    24
#define H_OUT   1024
#define W_OUT   1920
#define W4      (W_OUT / 4)     // 480
#define HW      (H_IN * W_IN)
#define PAD     (MAXD - 1)      // 23 zero-pad float4s for negative shifts

// Per-batch role block counts
#define DISP_BLKS    128        // one per input row
#define RESIZE_BLKS  240        // 128 rows * 480 float4-cols / 256 threads
#define SEG          (8 + 15)   // interleave: 8 disp + 15 resize per 23 bids
#define NSEG_BLKS    (DISP_BLKS + RESIZE_BLKS)          // 368
#define TOTAL_BLKS   (DISP_BLKS + 15 * NSEG_BLKS + RESIZE_BLKS)  // 5888

// Low-res disparity prediction scratch (pred * 8): ~2 MB.
__device__ float g_pred[BATCH * H_IN * W_IN];
// Per-batch disp-completion counters.
__device__ int   g_done[BATCH];

__global__ void reset_kernel() {
    if (threadIdx.x < BATCH) g_done[threadIdx.x] = 0;
}

// ---------------------------------------------------------------------------
// Pipelined kernel. Block id -> (role, batch-chunk, local id) such that the
// in-order block scheduler co-schedules disp(batch c+1) with resize(batch c):
//   bids [0,128)           : disp  b=0
//   15 segments of 368     : interleaved disp b=c+1 (8/23) + resize b=c (15/23)
//   last 240               : resize b=15
// disp blocks signal per-batch counters; resize blocks spin (thread 0 +
// __nanosleep) until their batch's 128 disp blocks are done.
// ---------------------------------------------------------------------------
__global__ __launch_bounds__(256) void pipe_kernel(
    const float* __restrict__ fl, const float* __restrict__ fr,
    float* __restrict__ out)
{
    const int bid = blockIdx.x;
    const int tid = threadIdx.x;

    int role, chunk, local;
    if (bid < DISP_BLKS) {
        role = 0; chunk = 0; local = bid;
    } else if (bid < DISP_BLKS + 15 * NSEG_BLKS) {
        const int p = bid - DISP_BLKS;
        const int c = p / NSEG_BLKS;
        const int q = p - c * NSEG_BLKS;          // 0..367
        const int grp = q / SEG;                  // 0..15
        const int pos = q - grp * SEG;            // 0..22
        if (pos < 8) { role = 0; chunk = c + 1; local = grp * 8 + pos; }
        else         { role = 1; chunk = c;     local = grp * 15 + (pos - 8); }
    } else {
        role = 1; chunk = 15; local = bid - (DISP_BLKS + 15 * NSEG_BLKS);
    }

    if (role == 0) {
        // =========== DISP: one (b, y) row ===========
        const int b = chunk, y = local;
        __shared__ float4 sr4[PAD + W_IN];

        if (tid < PAD) sr4[tid] = make_float4(0.f, 0.f, 0.f, 0.f);

        float4 L;
        const int x = tid;
        if (x < W_IN) {
            const size_t rb = (size_t)b * (CHAN * HW) + (size_t)y * W_IN + x;
            float4 R;
            R.x = fr[rb];          R.y = fr[rb + HW];
            R.z = fr[rb + 2 * HW]; R.w = fr[rb + 3 * HW];
            sr4[PAD + x] = R;
            L.x = fl[rb];          L.y = fl[rb + HW];
            L.z = fl[rb + 2 * HW]; L.w = fl[rb + 3 * HW];
        }
        __syncthreads();

        if (x < W_IN) {
            const float4* __restrict__ rrow = &sr4[PAD + x];
            float num = 0.0f, den = 0.0f;
#pragma unroll
            for (int d = 0; d < MAXD; d++) {
                const float4 R = rrow[-d];        // pad keeps this in-bounds
                const float c = fabsf(L.x - R.x) + fabsf(L.y - R.y)
                              + fabsf(L.z - R.z) + fabsf(L.w - R.w);
                const float e = __expf(-c);       // softmax(-cost), unshifted
                den += e;
                num += (float)d * e;
            }
            g_pred[(b * H_IN + y) * W_IN + x] = (num / den) * 8.0f;
        }
        // publish: make pred row visible, then bump the batch counter
        __syncthreads();
        __threadfence();
        if (tid == 0) atomicAdd(&g_done[b], 1);
    } else {
        // =========== RESIZE: 256 threads, batch = chunk ===========
        const int b = chunk;
        const int idx = local * 256 + tid;        // 0..61439
        const int g = idx % W4;
        const int r = idx / W4;                   // 0..127

        const float xsc = 239.0f / 1919.0f;
        const float ysc = 127.0f / 1023.0f;

        // pred-independent x-geometry (runs during the spin window)
        const int ox0 = g * 4;
        const int q = (ox0 * 239) / 1919;
        float wx[4];
        bool  hi[4];
#pragma unroll
        for (int k = 0; k < 4; k++) {
            const float xf = (float)(ox0 + k) * xsc;
            const int x0 = (int)xf;
            wx[k] = xf - (float)x0;
            hi[k] = (x0 > q);
        }
        const int q1 = min(q + 1, W_IN - 1);
        const int q2 = min(q + 2, W_IN - 1);
        const int r1 = min(r + 1, H_IN - 1);
        const int oys = (r * (H_OUT - 1) + (H_IN - 2)) / (H_IN - 1);
        const int oye = min(H_OUT - 1,
            ((r + 1) * (H_OUT - 1) + (H_IN - 2)) / (H_IN - 1) - 1);

        // wait for this batch's disp rows
        if (tid == 0) {
            while (*(volatile int*)&g_done[b] < DISP_BLKS) __nanosleep(64);
        }
        __syncthreads();
        __threadfence();   // acquire: order pred reads after counter observe

        const float* __restrict__ p0r = g_pred + (b * H_IN + r)  * W_IN;
        const float* __restrict__ p1r = g_pred + (b * H_IN + r1) * W_IN;
        const float p00 = p0r[q], p01 = p0r[q1], p02 = p0r[q2];
        const float D0 = p1r[q]  - p00;
        const float D1 = p1r[q1] - p01;
        const float D2 = p1r[q2] - p02;

        float4* __restrict__ out4 =
            (float4*)out + (size_t)b * H_OUT * W4 + g;

        for (int oy = oys; oy <= oye; oy++) {
            const float wy = (float)oy * ysc - (float)r;
            const float v0 = p00 + wy * D0;       // y-lerp (3 FMA)
            const float v1 = p01 + wy * D1;
            const float v2 = p02 + wy * D2;
            const float d01 = v1 - v0;
            const float d12 = v2 - v1;

            float4 o;
#pragma unroll
            for (int k = 0; k < 4; k++) {
                const float base = hi[k] ? v1 : v0;
                const float del  = hi[k] ? d12 : d01;
                ((float*)&o)[k] = base + wx[k] * del;
            }
            out4[(size_t)oy * W4] = o;            // warp: 512B contiguous
        }
    }
}

extern "C" void kernel_launch(void* const* d_in, const int* in_sizes, int n_in,
                              void* d_out, int out_size)
{
    const float* feat_l = (const float*)d_in[0];
    const float* feat_r = (const float*)d_in[1];
    float* out = (float*)d_out;

    reset_kernel<<<1, 32>>>();
    pipe_kernel<<<TOTAL_BLKS, 256>>>(feat_l, feat_r, out);
}

// round 15
// speedup vs baseline: 1.2910x; 1.2910x over previous
#include <cuda_runtime.h>

// Problem constants (fixed by setup_inputs)
#define BATCH   16
#define CHAN    4
#define H_IN    128
#define W_IN    240
#define MAXD    24
#define H_OUT   1024
#define W_OUT   1920
#define W4      (W_OUT / 4)     // 480
#define HW      (H_IN * W_IN)
#define PAD     (MAXD - 1)      // 23 zero-pad float4s for negative shifts

#define PX      4               // pixels per disp thread
#define TPR     (W_IN / PX)     // 60 threads per row
#define RPB     4               // rows per disp block
#define DISP_GRID (BATCH * H_IN / RPB)   // 512

// Low-res disparity prediction scratch (pred * 8): ~2 MB.
__device__ float g_pred[BATCH * H_IN * W_IN];

// ---------------------------------------------------------------------------
// K1: cost volume + softmax expectation. One block per (b, 4-row group).
// Right rows staged zero-padded in smem (channel-packed float4). Each thread
// owns 4 adjacent pixels and slides a 4-wide register window over the right
// row: 27 LDS.128 per 4 pixels instead of 96. Unshifted softmax.
// ---------------------------------------------------------------------------
__global__ __launch_bounds__(256) void disp_kernel(
    const float* __restrict__ fl, const float* __restrict__ fr)
{
    const int blk = blockIdx.x;          // b*32 + rg
    const int b  = blk >> 5;
    const int rg = blk & 31;
    const int tid = threadIdx.x;

    __shared__ float4 sr4[RPB][PAD + W_IN];

    // zero pads (4 rows x 23)
    for (int i = tid; i < RPB * PAD; i += 256) {
        const int r = i / PAD;
        sr4[r][i - r * PAD] = make_float4(0.f, 0.f, 0.f, 0.f);
    }
    // stage 4 right rows, channel-packed
    for (int i = tid; i < RPB * CHAN * W_IN; i += 256) {      // 3840
        const int r   = i / (CHAN * W_IN);
        const int rem = i - r * (CHAN * W_IN);
        const int c   = rem / W_IN;
        const int x   = rem - c * W_IN;
        const int yy  = rg * RPB + r;
        ((float*)&sr4[r][PAD + x])[c] =
            fr[(((size_t)b * CHAN + c) * H_IN + yy) * W_IN + x];
    }
    __syncthreads();

    const int r    = tid >> 6;           // row in block (0..3)
    const int lane = tid & 63;           // 0..63, active < 60
    if (lane < TPR) {
        const int y  = rg * RPB + r;
        const int x0 = lane * PX;

        // left pixels -> registers (coalesced-ish scalar LDG)
        float4 L[PX];
        {
            const size_t rb = (size_t)b * (CHAN * HW) + (size_t)y * W_IN + x0;
#pragma unroll
            for (int j = 0; j < PX; j++) {
                L[j].x = fl[rb + j];
                L[j].y = fl[rb + j + HW];
                L[j].z = fl[rb + j + 2 * HW];
                L[j].w = fl[rb + j + 3 * HW];
            }
        }

        const float4* __restrict__ row = &sr4[r][PAD + x0];

        // sliding window W[j] = R[x0 + j - d]
        float4 W0 = row[0], W1 = row[1], W2 = row[2], W3 = row[3];
        float num[PX], den[PX];
#pragma unroll
        for (int j = 0; j < PX; j++) { num[j] = 0.f; den[j] = 0.f; }

#pragma unroll
        for (int d = 0; d < MAXD; d++) {
            const float4 R0 = W0, R1 = W1, R2 = W2, R3 = W3;
            {
                const float c0 = fabsf(L[0].x - R0.x) + fabsf(L[0].y - R0.y)
                               + fabsf(L[0].z - R0.z) + fabsf(L[0].w - R0.w);
                const float c1 = fabsf(L[1].x - R1.x) + fabsf(L[1].y - R1.y)
                               + fabsf(L[1].z - R1.z) + fabsf(L[1].w - R1.w);
                const float c2 = fabsf(L[2].x - R2.x) + fabsf(L[2].y - R2.y)
                               + fabsf(L[2].z - R2.z) + fabsf(L[2].w - R2.w);
                const float c3 = fabsf(L[3].x - R3.x) + fabsf(L[3].y - R3.y)
                               + fabsf(L[3].z - R3.z) + fabsf(L[3].w - R3.w);
                const float fd = (float)d;
                const float e0 = __expf(-c0), e1 = __expf(-c1);
                const float e2 = __expf(-c2), e3 = __expf(-c3);
                den[0] += e0; num[0] += fd * e0;
                den[1] += e1; num[1] += fd * e1;
                den[2] += e2; num[2] += fd * e2;
                den[3] += e3; num[3] += fd * e3;
            }
            // slide window down by one (register renaming under full unroll)
            W3 = W2; W2 = W1; W1 = W0;
            W0 = row[-(d + 1)];
        }

        float4 o;
        o.x = (num[0] / den[0]) * 8.0f;      // * (1024/128)
        o.y = (num[1] / den[1]) * 8.0f;
        o.z = (num[2] / den[2]) * 8.0f;
        o.w = (num[3] / den[3]) * 8.0f;
        *(float4*)&g_pred[((size_t)b * H_IN + y) * W_IN + x0] = o;
    }
}

// ---------------------------------------------------------------------------
// K2: bilinear upsample 128x240 -> 1024x1920 (align_corners).
// One thread per (b, input-row r, float4 column g). 983,040 threads.
// 480 float4/row = 15 warps exactly -> every warp store is 512B contiguous.
// Streaming stores (cs) since output ~= L2 capacity.
// ---------------------------------------------------------------------------
__global__ __launch_bounds__(256) void resize_kernel(float* __restrict__ out)
{
    const int idx = blockIdx.x * 256 + threadIdx.x;   // exact grid, no guard
    const int g = idx % W4;
    const int t = idx / W4;
    const int r = t & (H_IN - 1);
    const int b = t >> 7;

    const float xsc = 239.0f / 1919.0f;
    const float ysc = 127.0f / 1023.0f;

    // hoisted x-geometry for 4 contiguous output pixels
    const int ox0 = g * 4;
    const int q = (ox0 * 239) / 1919;            // exact base input cell
    float wx[4];
    bool  hi[4];
#pragma unroll
    for (int k = 0; k < 4; k++) {
        const float xf = (float)(ox0 + k) * xsc;
        const int x0 = (int)xf;
        wx[k] = xf - (float)x0;
        hi[k] = (x0 > q);                        // pixel lies in cell q+1
    }

    const int q1 = min(q + 1, W_IN - 1);
    const int q2 = min(q + 2, W_IN - 1);
    const int r1 = min(r + 1, H_IN - 1);

    // pred window (2 rows x 3 cols) into registers
    const float* __restrict__ p0r = g_pred + (b * H_IN + r)  * W_IN;
    const float* __restrict__ p1r = g_pred + (b * H_IN + r1) * W_IN;
    const float p00 = __ldg(p0r + q), p01 = __ldg(p0r + q1), p02 = __ldg(p0r + q2);
    const float D0 = __ldg(p1r + q)  - p00;
    const float D1 = __ldg(p1r + q1) - p01;
    const float D2 = __ldg(p1r + q2) - p02;

    // output rows owned by input row r: floor(oy*127/1023) == r
    const int oys = (r * (H_OUT - 1) + (H_IN - 2)) / (H_IN - 1);
    const int oye = min(H_OUT - 1,
        ((r + 1) * (H_OUT - 1) + (H_IN - 2)) / (H_IN - 1) - 1);

    float4* __restrict__ out4 =
        (float4*)out + (size_t)b * H_OUT * W4 + g;

    for (int oy = oys; oy <= oye; oy++) {
        const float wy = (float)oy * ysc - (float)r;
        const float v0 = p00 + wy * D0;          // y-lerp (3 FMA)
        const float v1 = p01 + wy * D1;
        const float v2 = p02 + wy * D2;
        const float d01 = v1 - v0;
        const float d12 = v2 - v1;

        float4 o;
#pragma unroll
        for (int k = 0; k < 4; k++) {
            const float base = hi[k] ? v1 : v0;
            const float del  = hi[k] ? d12 : d01;
            ((float*)&o)[k] = base + wx[k] * del;
        }
        __stcs(out4 + (size_t)oy * W4, o);       // streaming 512B warp store
    }
}

extern "C" void kernel_launch(void* const* d_in, const int* in_sizes, int n_in,
                              void* d_out, int out_size)
{
    const float* feat_l = (const float*)d_in[0];
    const float* feat_r = (const float*)d_in[1];
    float* out = (float*)d_out;

    disp_kernel<<<DISP_GRID, 256>>>(feat_l, feat_r);

    const int total = BATCH * H_IN * W4;         // 983,040
    resize_kernel<<<total / 256, 256>>>(out);
}